// round 12
// baseline (speedup 1.0000x reference)
#include <cuda_runtime.h>
#include <cstdint>
#include <cstddef>

#define BATCH   32
#define PRIORS  32768
#define NUMC    21
#define NCLS    20
#define NMSK    1000
#define TOPK    200
#define CONF_T  0.01f
#define NMS_T   0.3f
#define NT      256
#define T0F     0.95f
#define CAP     2048
#define BCAP    64

typedef unsigned long long ull;
#define FULL 0xffffffffu

__device__ float4 g_decoded[(size_t)BATCH * PRIORS];
__device__ ull    g_cand[(size_t)BATCH * NCLS * CAP];
__device__ int    g_cnt[BATCH * NCLS];       // zero-init at load; self-zeroed by nms
__device__ int    g_cntlow[BATCH * NCLS];
__device__ int    g_ovf[BATCH * NCLS];

// ---------------------------------------------------------------------------
// Kernel 1: fused decode + candidate gather (one pass over conf, staged in smem)
// ---------------------------------------------------------------------------
__global__ __launch_bounds__(NT) void prep_gather(const float* __restrict__ loc,
                                                  const float* __restrict__ conf,
                                                  const float* __restrict__ prior) {
    __shared__ __align__(16) float s_stage[NT * NUMC];   // 21504 B
    __shared__ ull s_cbuf[NCLS][BCAP];                   // 10240 B
    __shared__ int s_ccnt[NCLS], s_lowc[NCLS];

    const int blk = blockIdx.x, tid = threadIdx.x, lane = tid & 31, wid = tid >> 5;

    const float4* src = reinterpret_cast<const float4*>(conf + (size_t)blk * NT * NUMC);
    float4* st = reinterpret_cast<float4*>(s_stage);
    for (int i = tid; i < NT * NUMC / 4; i += NT) st[i] = src[i];
    if (tid < NCLS) { s_ccnt[tid] = 0; s_lowc[tid] = 0; }

    const int idx = blk * NT + tid;
    const int p   = idx & (PRIORS - 1);
    const int b   = idx >> 15;
    {
        float4 l  = reinterpret_cast<const float4*>(loc)[idx];
        float4 pr = reinterpret_cast<const float4*>(prior)[p];
        float cx = pr.x + (l.x * 0.1f) * pr.z;
        float cy = pr.y + (l.y * 0.1f) * pr.w;
        float w  = pr.z * expf(l.z * 0.2f);
        float h  = pr.w * expf(l.w * 0.2f);
        float x1 = cx - w * 0.5f;
        float y1 = cy - h * 0.5f;
        g_decoded[idx] = make_float4(x1, y1, x1 + w, y1 + h);
    }
    __syncthreads();

    const float* row = s_stage + tid * NUMC;
#pragma unroll
    for (int c = 0; c < NCLS; ++c) {
        float x = row[c + 1];
        bool pass = (x > T0F);
        bool low  = (x > CONF_T) && !pass;
        unsigned int pm = __ballot_sync(FULL, pass);
        unsigned int lm = __ballot_sync(FULL, low);
        if (pm) {
            int leader = __ffs(pm) - 1;
            int n = __popc(pm);
            int base;
            if (lane == leader) base = atomicAdd(&s_ccnt[c], n);
            base = __shfl_sync(FULL, base, leader);
            if (pass) {
                int pos = base + __popc(pm & ((1u << lane) - 1u));
                if (pos < BCAP)
                    s_cbuf[c][pos] = ((ull)__float_as_uint(x) << 32)
                                   | (ull)(0xFFFFFFFFu - (unsigned int)p);
            }
        }
        if (lm && lane == __ffs(lm) - 1) atomicAdd(&s_lowc[c], __popc(lm));
    }
    __syncthreads();

    for (int c = wid; c < NCLS; c += 8) {
        int bc = b * NCLS + c;
        int n  = s_ccnt[c];
        int ov = (n > BCAP);
        if (ov) n = BCAP;
        int gbase;
        if (lane == 0) gbase = atomicAdd(&g_cnt[bc], n);
        gbase = __shfl_sync(FULL, gbase, 0);
        if (gbase + n > CAP) ov = 1;
        for (int i = lane; i < n; i += 32) {
            int q = gbase + i;
            if (q < CAP) g_cand[(size_t)bc * CAP + q] = s_cbuf[c][i];
        }
        if (lane == 0) {
            if (ov) atomicExch(&g_ovf[bc], 1);
            int lw = s_lowc[c];
            if (lw) atomicAdd(&g_cntlow[bc], lw);
        }
    }
}

// ---------------------------------------------------------------------------
// Kernel 2: per (batch,class) top-1000 select + forward block-parallel NMS
// ---------------------------------------------------------------------------
__global__ __launch_bounds__(NT) void nms_kernel(float* __restrict__ out,
                                                 const float* __restrict__ conf) {
    const int bx = blockIdx.x, b = bx / NUMC, cc = bx % NUMC;
    const int tid = threadIdx.x;
    float* outp = out + (size_t)bx * (TOPK * 5);

    if (cc == 0) {
        for (int i = tid; i < TOPK * 5; i += NT) outp[i] = 0.f;
        return;
    }
    const int bc = b * NCLS + (cc - 1);

    __shared__ __align__(16) unsigned char s_mem[28672];
    ull*    s_keys = reinterpret_cast<ull*>(s_mem);            // [0,16K)
    ull*    s_dst  = reinterpret_cast<ull*>(s_mem + 16384);    // [16K,24K)
    int*    s_hist = reinterpret_cast<int*>(s_mem);            // fallback alias
    float4* s_box  = reinterpret_cast<float4*>(s_mem);         // [0,16K) late
    float*  s_val  = reinterpret_cast<float*>(s_mem + 24576);  // [24K,28K)
    __shared__ int s_shist[256];
    __shared__ unsigned int s_sup[32];
    __shared__ int s_keep[TOPK];
    __shared__ int s_cnt2, s_pivch, s_pivkk, s_pivbin, s_selb, s_sab, s_pc;
    __shared__ unsigned int s_umax;

    const int lane = tid & 31;
    const int wid  = tid >> 5;

    int cnt = g_cnt[bc];
    bool need_fb = g_ovf[bc] || (cnt > CAP) || (cnt < NMSK && g_cntlow[bc] > 0);
    unsigned int Tgt = __float_as_uint(T0F);

    if (tid == 0) s_umax = 0u;
    __syncthreads();

    if (!need_fb) {
        const ull* cand = g_cand + (size_t)bc * CAP;
        unsigned int um = 0u;
        for (int i = tid; i < cnt; i += NT) {
            ull k = __ldg(cand + i);
            s_keys[i] = k;
            unsigned int bits = (unsigned int)(k >> 32);
            um = um > bits ? um : bits;
        }
#pragma unroll
        for (int o = 16; o; o >>= 1) {
            unsigned int t = __shfl_down_sync(FULL, um, o);
            um = um > t ? um : t;
        }
        if (lane == 0) atomicMax(&s_umax, um);
        __syncthreads();
    } else {
        const float* base = conf + ((size_t)b << 15) * NUMC + cc;
        for (int i = tid; i < 4096; i += NT) s_hist[i] = 0;
        if (tid == 0) s_pivch = -1;
        __syncthreads();
        for (int i = tid; i < PRIORS; i += NT) {
            float x = __ldg(base + (size_t)i * NUMC);
            unsigned int bits = (x > CONF_T) ? __float_as_uint(x) : 0u;
            atomicAdd(&s_hist[bits >> 20], 1);
        }
        __syncthreads();
        { int cs = 0; for (int j = 0; j < 16; ++j) cs += s_hist[tid * 16 + j]; s_shist[tid] = cs; }
        __syncthreads();
        for (int d = 1; d < 256; d <<= 1) {
            int v = (tid + d < 256) ? s_shist[tid + d] : 0;
            __syncthreads();
            s_shist[tid] += v;
            __syncthreads();
        }
        { int suf = s_shist[tid]; int sufn = (tid < 255) ? s_shist[tid + 1] : 0;
          if (suf >= NMSK && sufn < NMSK) { s_pivch = tid; s_pivkk = NMSK - sufn; } }
        __syncthreads();
        if (tid == 0) {
            int pb = 1;
            if (s_pivch >= 0) {
                int ch = s_pivch, kk = s_pivkk, run = 0;
                for (int j = 15; j >= 0; --j) {
                    run += s_hist[ch * 16 + j];
                    if (run >= kk) { pb = ch * 16 + j; break; }
                }
            }
            if (pb < 1) pb = 1;
            s_pivbin = pb; s_cnt2 = 0; s_umax = 0u;
        }
        __syncthreads();
        Tgt = (((unsigned int)s_pivbin) << 20) - 1u;
        unsigned int um = 0u;
        for (int i = tid; i < PRIORS; i += NT) {
            float x = __ldg(base + (size_t)i * NUMC);
            unsigned int bits = __float_as_uint(x);
            if (x > CONF_T && bits > Tgt) {
                int pos = atomicAdd(&s_cnt2, 1);
                if (pos < CAP)
                    s_keys[pos] = ((ull)bits << 32) | (ull)(0xFFFFFFFFu - (unsigned int)i);
                um = um > bits ? um : bits;
            }
        }
#pragma unroll
        for (int o = 16; o; o >>= 1) {
            unsigned int t = __shfl_down_sync(FULL, um, o);
            um = um > t ? um : t;
        }
        if (lane == 0) atomicMax(&s_umax, um);
        __syncthreads();
        cnt = s_cnt2; if (cnt > CAP - 1) cnt = CAP - 1;
    }

    // ---------- refine to <=1024 ----------
    bool sorted2048 = false;
    int sabove = cnt;
    if (cnt > 1024) {
        unsigned int base = Tgt;
        unsigned int span = s_umax - base;
        int nbits = 32 - __clz((int)span);
        int shift = nbits > 8 ? nbits - 8 : 0;
        s_shist[tid] = 0;
        if (tid == 0) s_selb = -1;
        __syncthreads();
        for (int i = tid; i < cnt; i += NT) {
            unsigned int bits = (unsigned int)(s_keys[i] >> 32);
            atomicAdd(&s_shist[(bits - base) >> shift], 1);
        }
        __syncthreads();
        if (wid == 0) {
            int base8 = lane * 8;
            int h[8]; int s = 0;
#pragma unroll
            for (int j = 0; j < 8; ++j) { h[j] = s_shist[base8 + j]; s += h[j]; }
            int suf = s;
#pragma unroll
            for (int o = 1; o < 32; o <<= 1) {
                int t = __shfl_down_sync(FULL, suf, o);
                if (lane + o < 32) suf += t;
            }
            int sufn = __shfl_down_sync(FULL, suf, 1);
            if (lane == 31) sufn = 0;
            if (suf >= NMSK && sufn < NMSK) {
                int run = 0;
#pragma unroll
                for (int j = 7; j >= 0; --j) {
                    run += h[j];
                    if (sufn + run >= NMSK) { s_selb = base8 + j; s_sab = sufn + run; break; }
                }
            }
        }
        __syncthreads();
        int selb = s_selb;
        if (selb >= 0 && s_sab <= 1024) {
            unsigned int T2 = base + (((unsigned int)selb) << shift);
            if (tid == 0) s_pc = 0;
            for (int i = tid; i < 1024; i += NT) s_dst[i] = 0ull;
            __syncthreads();
            for (int i = tid; i < cnt; i += NT) {
                ull k = s_keys[i];
                if ((unsigned int)(k >> 32) >= T2) {
                    int p = atomicAdd(&s_pc, 1);
                    if (p < 1024) s_dst[p] = k;
                }
            }
            sabove = s_sab;
        } else {
            for (int i = cnt + tid; i < 2048; i += NT) s_keys[i] = 0ull;
            for (int k2 = 2; k2 <= 2048; k2 <<= 1) {
                for (int j = k2 >> 1; j > 0; j >>= 1) {
                    if (j >= 16) __syncthreads(); else __syncwarp();
                    for (int i = tid; i < 2048; i += NT) {
                        int l = i ^ j;
                        if (l > i) {
                            ull a = s_keys[i], bb = s_keys[l];
                            bool up = ((i & k2) == 0);
                            if (up ? (a < bb) : (a > bb)) { s_keys[i] = bb; s_keys[l] = a; }
                        }
                    }
                }
            }
            __syncthreads();
            for (int i = tid; i < 1024; i += NT) s_dst[i] = (i < NMSK) ? s_keys[i] : 0ull;
            sorted2048 = true;
        }
    } else {
        for (int i = tid; i < 1024; i += NT) s_dst[i] = (i < cnt) ? s_keys[i] : 0ull;
    }
    __syncthreads();
    if (!sorted2048) {
        for (int k2 = 2; k2 <= 1024; k2 <<= 1) {
            for (int j = k2 >> 1; j > 0; j >>= 1) {
                if (j >= 16) __syncthreads(); else __syncwarp();
                for (int i = tid; i < 1024; i += NT) {
                    int l = i ^ j;
                    if (l > i) {
                        ull a = s_dst[i], bb = s_dst[l];
                        bool up = ((i & k2) == 0);
                        if (up ? (a < bb) : (a > bb)) { s_dst[i] = bb; s_dst[l] = a; }
                    }
                }
            }
        }
        __syncthreads();
    }

    // ---------- extract boxes (s_box aliases dead s_keys) ----------
    const float4* dec = g_decoded + ((size_t)b << 15);
    const int nvalid = sabove < NMSK ? sabove : NMSK;
    for (int r = tid; r < 1024; r += NT) {
        float v = 0.f;
        float4 bb = make_float4(0.f, 0.f, 0.f, 0.f);
        if (r < NMSK) {
            ull key = s_dst[r];
            unsigned int bits = (unsigned int)(key >> 32);
            v = __uint_as_float(bits);
            if (v > CONF_T) {
                unsigned int p = 0xFFFFFFFFu - (unsigned int)(key & 0xFFFFFFFFull);
                bb = __ldg(dec + p);
            } else v = 0.f;
        }
        s_box[r] = bb;
        s_val[r] = v;
    }
    if (tid < 32) s_sup[tid] = 0u;
    __syncthreads();

    // ---------- forward block-parallel greedy NMS with skip-scan cursor ----------
    // One loop iteration per KEPT candidate. All threads redundantly scan the
    // suppression bitmask for the next unsuppressed k (consistent post-barrier),
    // then 256 threads suppress followers. One barrier per kept candidate.
    int nkeep = 0;
    int cursor = 0;
    while (cursor < nvalid) {
        // find next unsuppressed candidate >= cursor (redundant in every thread)
        int k = cursor;
        unsigned int wmask = ~s_sup[k >> 5] & (0xffffffffu << (k & 31));
        while (true) {
            if (wmask) { k = (k & ~31) + __ffs(wmask) - 1; break; }
            k = (k & ~31) + 32;
            if (k >= nvalid) break;
            wmask = ~s_sup[k >> 5];
        }
        if (k >= nvalid || s_val[k] <= CONF_T) break;

        if (tid == 0) s_keep[nkeep] = k;
        nkeep++;                                   // uniform across block
        if (nkeep >= TOPK) break;                  // 200th keep: no suppression needed

        float4 bk = s_box[k];
        float ka = (bk.z - bk.x) * (bk.w - bk.y);
        for (int j = k + 1 + tid; j < nvalid; j += NT) {
            if ((s_sup[j >> 5] >> (j & 31)) & 1u) continue;
            float4 bj = s_box[j];
            float aj = (bj.z - bj.x) * (bj.w - bj.y);
            float w = fminf(bj.z, bk.z) - fmaxf(bj.x, bk.x);
            float h = fminf(bj.w, bk.w) - fmaxf(bj.y, bk.y);
            w = fmaxf(w, 0.f); h = fmaxf(h, 0.f);
            float inter = w * h;
            if (inter / (aj + ka - inter) > NMS_T)
                atomicOr(&s_sup[j >> 5], 1u << (j & 31));
        }
        cursor = k + 1;
        __syncthreads();                           // order atomicOrs before next scan
    }
    __syncthreads();

    // ---------- write output + self-zero counters ----------
    for (int r = tid; r < TOPK; r += NT) {
        float e0 = 0.f, e1 = 0.f, e2 = 0.f, e3 = 0.f, e4 = 0.f;
        if (r < nkeep) {
            int k = s_keep[r];
            float4 bk = s_box[k];
            e0 = s_val[k]; e1 = bk.x; e2 = bk.y; e3 = bk.z; e4 = bk.w;
        }
        float* row = outp + r * 5;
        row[0] = e0; row[1] = e1; row[2] = e2; row[3] = e3; row[4] = e4;
    }
    if (tid == 0) { g_cnt[bc] = 0; g_cntlow[bc] = 0; g_ovf[bc] = 0; }
}

// ---------------------------------------------------------------------------
extern "C" void kernel_launch(void* const* d_in, const int* in_sizes, int n_in,
                              void* d_out, int out_size) {
    const float *loc = nullptr, *conf = nullptr, *prior = nullptr;
    for (int i = 0; i < n_in; ++i) {
        long long sz = in_sizes[i];
        if      (sz == (long long)BATCH * PRIORS * 4)    loc   = (const float*)d_in[i];
        else if (sz == (long long)BATCH * PRIORS * NUMC) conf  = (const float*)d_in[i];
        else if (sz == (long long)PRIORS * 4)            prior = (const float*)d_in[i];
    }
    prep_gather<<<BATCH * PRIORS / NT, NT>>>(loc, conf, prior);
    nms_kernel<<<BATCH * NUMC, NT>>>((float*)d_out, conf);
    (void)out_size;
}

// round 13
// speedup vs baseline: 2.5114x; 2.5114x over previous
#include <cuda_runtime.h>
#include <cstdint>
#include <cstddef>

#define BATCH   32
#define PRIORS  32768
#define NUMC    21
#define NCLS    20
#define NMSK    1000
#define TOPK    200
#define CONF_T  0.01f
#define NMS_T   0.3f
#define NT      256
#define T0F     0.95f
#define CAP     2048
#define BCAP    64

typedef unsigned long long ull;
#define FULL 0xffffffffu

__device__ float4 g_decoded[(size_t)BATCH * PRIORS];
__device__ ull    g_cand[(size_t)BATCH * NCLS * CAP];
__device__ int    g_cnt[BATCH * NCLS];       // zero-init at load; self-zeroed by nms
__device__ int    g_cntlow[BATCH * NCLS];
__device__ int    g_ovf[BATCH * NCLS];

// ---------------------------------------------------------------------------
// Kernel 1: fused decode + candidate gather (one pass over conf, staged in smem)
// ---------------------------------------------------------------------------
__global__ __launch_bounds__(NT) void prep_gather(const float* __restrict__ loc,
                                                  const float* __restrict__ conf,
                                                  const float* __restrict__ prior) {
    __shared__ __align__(16) float s_stage[NT * NUMC];   // 21504 B
    __shared__ ull s_cbuf[NCLS][BCAP];                   // 10240 B
    __shared__ int s_ccnt[NCLS], s_lowc[NCLS];

    const int blk = blockIdx.x, tid = threadIdx.x, lane = tid & 31, wid = tid >> 5;

    const float4* src = reinterpret_cast<const float4*>(conf + (size_t)blk * NT * NUMC);
    float4* st = reinterpret_cast<float4*>(s_stage);
    for (int i = tid; i < NT * NUMC / 4; i += NT) st[i] = src[i];
    if (tid < NCLS) { s_ccnt[tid] = 0; s_lowc[tid] = 0; }

    const int idx = blk * NT + tid;
    const int p   = idx & (PRIORS - 1);
    const int b   = idx >> 15;
    {
        float4 l  = reinterpret_cast<const float4*>(loc)[idx];
        float4 pr = reinterpret_cast<const float4*>(prior)[p];
        float cx = pr.x + (l.x * 0.1f) * pr.z;
        float cy = pr.y + (l.y * 0.1f) * pr.w;
        float w  = pr.z * expf(l.z * 0.2f);
        float h  = pr.w * expf(l.w * 0.2f);
        float x1 = cx - w * 0.5f;
        float y1 = cy - h * 0.5f;
        g_decoded[idx] = make_float4(x1, y1, x1 + w, y1 + h);
    }
    __syncthreads();

    const float* row = s_stage + tid * NUMC;
#pragma unroll
    for (int c = 0; c < NCLS; ++c) {
        float x = row[c + 1];
        bool pass = (x > T0F);
        bool low  = (x > CONF_T) && !pass;
        unsigned int pm = __ballot_sync(FULL, pass);
        unsigned int lm = __ballot_sync(FULL, low);
        if (pm) {
            int leader = __ffs(pm) - 1;
            int n = __popc(pm);
            int base;
            if (lane == leader) base = atomicAdd(&s_ccnt[c], n);
            base = __shfl_sync(FULL, base, leader);
            if (pass) {
                int pos = base + __popc(pm & ((1u << lane) - 1u));
                if (pos < BCAP)
                    s_cbuf[c][pos] = ((ull)__float_as_uint(x) << 32)
                                   | (ull)(0xFFFFFFFFu - (unsigned int)p);
            }
        }
        if (lm && lane == __ffs(lm) - 1) atomicAdd(&s_lowc[c], __popc(lm));
    }
    __syncthreads();

    for (int c = wid; c < NCLS; c += 8) {
        int bc = b * NCLS + c;
        int n  = s_ccnt[c];
        int ov = (n > BCAP);
        if (ov) n = BCAP;
        int gbase;
        if (lane == 0) gbase = atomicAdd(&g_cnt[bc], n);
        gbase = __shfl_sync(FULL, gbase, 0);
        if (gbase + n > CAP) ov = 1;
        for (int i = lane; i < n; i += 32) {
            int q = gbase + i;
            if (q < CAP) g_cand[(size_t)bc * CAP + q] = s_cbuf[c][i];
        }
        if (lane == 0) {
            if (ov) atomicExch(&g_ovf[bc], 1);
            int lw = s_lowc[c];
            if (lw) atomicAdd(&g_cntlow[bc], lw);
        }
    }
}

// ---------------------------------------------------------------------------
// Kernel 2: per (batch,class) top-1000 select + batched-speculative greedy NMS
// ---------------------------------------------------------------------------
__global__ __launch_bounds__(NT) void nms_kernel(float* __restrict__ out,
                                                 const float* __restrict__ conf) {
    const int bx = blockIdx.x, b = bx / NUMC, cc = bx % NUMC;
    const int tid = threadIdx.x;
    float* outp = out + (size_t)bx * (TOPK * 5);

    if (cc == 0) {
        for (int i = tid; i < TOPK * 5; i += NT) outp[i] = 0.f;
        return;
    }
    const int bc = b * NCLS + (cc - 1);

    __shared__ __align__(16) unsigned char s_mem[28672];
    ull*    s_keys = reinterpret_cast<ull*>(s_mem);            // [0,16K)
    ull*    s_dst  = reinterpret_cast<ull*>(s_mem + 16384);    // [16K,24K)
    int*    s_hist = reinterpret_cast<int*>(s_mem);            // fallback alias
    float4* s_box  = reinterpret_cast<float4*>(s_mem);         // [0,16K) late
    float*  s_val  = reinterpret_cast<float*>(s_mem + 24576);  // [24K,28K)
    __shared__ int s_shist[256];
    __shared__ float4 s_kbox[TOPK];
    __shared__ float  s_karea[TOPK];
    __shared__ int    s_keep[TOPK];
    __shared__ int    s_tri[32];
    __shared__ int    s_supin[32];
    __shared__ int s_cnt2, s_pivch, s_pivkk, s_pivbin, s_selb, s_sab, s_pc, s_nk;
    __shared__ unsigned int s_umax;

    const int lane = tid & 31;
    const int wid  = tid >> 5;

    int cnt = g_cnt[bc];
    bool need_fb = g_ovf[bc] || (cnt > CAP) || (cnt < NMSK && g_cntlow[bc] > 0);
    unsigned int Tgt = __float_as_uint(T0F);

    if (tid == 0) s_umax = 0u;
    __syncthreads();

    if (!need_fb) {
        const ull* cand = g_cand + (size_t)bc * CAP;
        unsigned int um = 0u;
        for (int i = tid; i < cnt; i += NT) {
            ull k = __ldg(cand + i);
            s_keys[i] = k;
            unsigned int bits = (unsigned int)(k >> 32);
            um = um > bits ? um : bits;
        }
#pragma unroll
        for (int o = 16; o; o >>= 1) {
            unsigned int t = __shfl_down_sync(FULL, um, o);
            um = um > t ? um : t;
        }
        if (lane == 0) atomicMax(&s_umax, um);
        __syncthreads();
    } else {
        const float* base = conf + ((size_t)b << 15) * NUMC + cc;
        for (int i = tid; i < 4096; i += NT) s_hist[i] = 0;
        if (tid == 0) s_pivch = -1;
        __syncthreads();
        for (int i = tid; i < PRIORS; i += NT) {
            float x = __ldg(base + (size_t)i * NUMC);
            unsigned int bits = (x > CONF_T) ? __float_as_uint(x) : 0u;
            atomicAdd(&s_hist[bits >> 20], 1);
        }
        __syncthreads();
        { int cs = 0; for (int j = 0; j < 16; ++j) cs += s_hist[tid * 16 + j]; s_shist[tid] = cs; }
        __syncthreads();
        for (int d = 1; d < 256; d <<= 1) {
            int v = (tid + d < 256) ? s_shist[tid + d] : 0;
            __syncthreads();
            s_shist[tid] += v;
            __syncthreads();
        }
        { int suf = s_shist[tid]; int sufn = (tid < 255) ? s_shist[tid + 1] : 0;
          if (suf >= NMSK && sufn < NMSK) { s_pivch = tid; s_pivkk = NMSK - sufn; } }
        __syncthreads();
        if (tid == 0) {
            int pb = 1;
            if (s_pivch >= 0) {
                int ch = s_pivch, kk = s_pivkk, run = 0;
                for (int j = 15; j >= 0; --j) {
                    run += s_hist[ch * 16 + j];
                    if (run >= kk) { pb = ch * 16 + j; break; }
                }
            }
            if (pb < 1) pb = 1;
            s_pivbin = pb; s_cnt2 = 0; s_umax = 0u;
        }
        __syncthreads();
        Tgt = (((unsigned int)s_pivbin) << 20) - 1u;
        unsigned int um = 0u;
        for (int i = tid; i < PRIORS; i += NT) {
            float x = __ldg(base + (size_t)i * NUMC);
            unsigned int bits = __float_as_uint(x);
            if (x > CONF_T && bits > Tgt) {
                int pos = atomicAdd(&s_cnt2, 1);
                if (pos < CAP)
                    s_keys[pos] = ((ull)bits << 32) | (ull)(0xFFFFFFFFu - (unsigned int)i);
                um = um > bits ? um : bits;
            }
        }
#pragma unroll
        for (int o = 16; o; o >>= 1) {
            unsigned int t = __shfl_down_sync(FULL, um, o);
            um = um > t ? um : t;
        }
        if (lane == 0) atomicMax(&s_umax, um);
        __syncthreads();
        cnt = s_cnt2; if (cnt > CAP - 1) cnt = CAP - 1;
    }

    // ---------- refine to <=1024 ----------
    bool sorted2048 = false;
    int sabove = cnt;
    if (cnt > 1024) {
        unsigned int base = Tgt;
        unsigned int span = s_umax - base;
        int nbits = 32 - __clz((int)span);
        int shift = nbits > 8 ? nbits - 8 : 0;
        s_shist[tid] = 0;
        if (tid == 0) s_selb = -1;
        __syncthreads();
        for (int i = tid; i < cnt; i += NT) {
            unsigned int bits = (unsigned int)(s_keys[i] >> 32);
            atomicAdd(&s_shist[(bits - base) >> shift], 1);
        }
        __syncthreads();
        if (wid == 0) {
            int base8 = lane * 8;
            int h[8]; int s = 0;
#pragma unroll
            for (int j = 0; j < 8; ++j) { h[j] = s_shist[base8 + j]; s += h[j]; }
            int suf = s;
#pragma unroll
            for (int o = 1; o < 32; o <<= 1) {
                int t = __shfl_down_sync(FULL, suf, o);
                if (lane + o < 32) suf += t;
            }
            int sufn = __shfl_down_sync(FULL, suf, 1);
            if (lane == 31) sufn = 0;
            if (suf >= NMSK && sufn < NMSK) {
                int run = 0;
#pragma unroll
                for (int j = 7; j >= 0; --j) {
                    run += h[j];
                    if (sufn + run >= NMSK) { s_selb = base8 + j; s_sab = sufn + run; break; }
                }
            }
        }
        __syncthreads();
        int selb = s_selb;
        if (selb >= 0 && s_sab <= 1024) {
            unsigned int T2 = base + (((unsigned int)selb) << shift);
            if (tid == 0) s_pc = 0;
            for (int i = tid; i < 1024; i += NT) s_dst[i] = 0ull;
            __syncthreads();
            for (int i = tid; i < cnt; i += NT) {
                ull k = s_keys[i];
                if ((unsigned int)(k >> 32) >= T2) {
                    int p = atomicAdd(&s_pc, 1);
                    if (p < 1024) s_dst[p] = k;
                }
            }
            sabove = s_sab;
        } else {
            for (int i = cnt + tid; i < 2048; i += NT) s_keys[i] = 0ull;
            for (int k2 = 2; k2 <= 2048; k2 <<= 1) {
                for (int j = k2 >> 1; j > 0; j >>= 1) {
                    if (j >= 16) __syncthreads(); else __syncwarp();
                    for (int i = tid; i < 2048; i += NT) {
                        int l = i ^ j;
                        if (l > i) {
                            ull a = s_keys[i], bb = s_keys[l];
                            bool up = ((i & k2) == 0);
                            if (up ? (a < bb) : (a > bb)) { s_keys[i] = bb; s_keys[l] = a; }
                        }
                    }
                }
            }
            __syncthreads();
            for (int i = tid; i < 1024; i += NT) s_dst[i] = (i < NMSK) ? s_keys[i] : 0ull;
            sorted2048 = true;
        }
    } else {
        for (int i = tid; i < 1024; i += NT) s_dst[i] = (i < cnt) ? s_keys[i] : 0ull;
    }
    __syncthreads();
    if (!sorted2048) {
        for (int k2 = 2; k2 <= 1024; k2 <<= 1) {
            for (int j = k2 >> 1; j > 0; j >>= 1) {
                if (j >= 16) __syncthreads(); else __syncwarp();
                for (int i = tid; i < 1024; i += NT) {
                    int l = i ^ j;
                    if (l > i) {
                        ull a = s_dst[i], bb = s_dst[l];
                        bool up = ((i & k2) == 0);
                        if (up ? (a < bb) : (a > bb)) { s_dst[i] = bb; s_dst[l] = a; }
                    }
                }
            }
        }
        __syncthreads();
    }

    // ---------- extract boxes (s_box aliases dead s_keys) ----------
    const float4* dec = g_decoded + ((size_t)b << 15);
    const int nvalid = sabove < NMSK ? sabove : NMSK;
    for (int r = tid; r < 1024; r += NT) {
        float v = 0.f;
        float4 bb = make_float4(0.f, 0.f, 0.f, 0.f);
        if (r < NMSK) {
            ull key = s_dst[r];
            unsigned int bits = (unsigned int)(key >> 32);
            v = __uint_as_float(bits);
            if (v > CONF_T) {
                unsigned int p = 0xFFFFFFFFu - (unsigned int)(key & 0xFFFFFFFFull);
                bb = __ldg(dec + p);
            } else v = 0.f;
        }
        s_box[r] = bb;
        s_val[r] = v;
    }
    __syncthreads();

    // ---------- batched-speculative greedy NMS (exact; 32 candidates/batch) ----------
    int nk = 0;
    const int nbatch = (nvalid + 31) >> 5;
    for (int bt = 0; bt < nbatch; ++bt) {
        const int B0 = bt << 5;
        if (s_val[B0] <= CONF_T) break;          // sorted: rest invalid (uniform)
        if (tid < 32) s_supin[tid] = 0;
        __syncthreads();

        // Phase 1: thread (wid,lane) tests candidate B0+lane vs kept strip wid,+8,...
        {
            int c = B0 + lane;
            float vc = s_val[c];
            if (vc > CONF_T) {
                float4 bcx = s_box[c];
                float acx = (bcx.z - bcx.x) * (bcx.w - bcx.y);
                bool sup = false;
                for (int j = wid; j < nk; j += 8) {
                    float4 ba = s_kbox[j];          // broadcast across lanes
                    float w = fminf(bcx.z, ba.z) - fmaxf(bcx.x, ba.x);
                    float h = fminf(bcx.w, ba.w) - fmaxf(bcx.y, ba.y);
                    w = fmaxf(w, 0.f); h = fmaxf(h, 0.f);
                    float inter = w * h;
                    sup = sup || (inter / (acx + s_karea[j] - inter) > NMS_T);
                }
                if (sup) s_supin[lane] = 1;         // benign race (same value)
            }
        }
        __syncthreads();

        // Phase 2: warp 0 — intra-batch triangle + greedy chain + append keeps
        if (wid == 0) {
            int c = B0 + lane;
            float4 bcx = s_box[c];
            float vc = s_val[c];
            float acx = (bcx.z - bcx.x) * (bcx.w - bcx.y);
            unsigned int vmask = __ballot_sync(FULL, vc > CONF_T);
            unsigned int supin = __ballot_sync(FULL, s_supin[lane] != 0);
            unsigned int inm = 0;                   // bits a<lane that suppress me
#pragma unroll 4
            for (int a = 0; a < 31; ++a) {
                float4 ba = s_box[B0 + a];          // broadcast
                float w = fminf(bcx.z, ba.z) - fmaxf(bcx.x, ba.x);
                float h = fminf(bcx.w, ba.w) - fmaxf(bcx.y, ba.y);
                w = fmaxf(w, 0.f); h = fmaxf(h, 0.f);
                float inter = w * h;
                float aa = (ba.z - ba.x) * (ba.w - ba.y);
                bool s = (a < lane) && (inter / (acx + aa - inter) > NMS_T);
                inm |= s ? (1u << a) : 0u;
            }
            s_tri[lane] = (int)inm;
            __syncwarp();
            // greedy chain replay (identical in every lane)
            unsigned int kept = 0;
            unsigned int elig = vmask & ~supin;
            int cap = TOPK - nk;
            int c2 = 0;
#pragma unroll 4
            for (int a = 0; a < 32; ++a) {
                if (c2 < cap && ((elig >> a) & 1u)
                    && (((unsigned int)s_tri[a] & kept) == 0u)) {
                    kept |= 1u << a; ++c2;
                }
            }
            if ((kept >> lane) & 1u) {
                int r = nk + __popc(kept & ((1u << lane) - 1u));
                s_kbox[r] = bcx; s_karea[r] = acx; s_keep[r] = c;
            }
            if (lane == 0) s_nk = nk + c2;
        }
        __syncthreads();
        nk = s_nk;
        if (nk >= TOPK) break;
    }
    __syncthreads();

    // ---------- write output + self-zero counters ----------
    int nkeep = nk < TOPK ? nk : TOPK;
    for (int r = tid; r < TOPK; r += NT) {
        float e0 = 0.f, e1 = 0.f, e2 = 0.f, e3 = 0.f, e4 = 0.f;
        if (r < nkeep) {
            int k = s_keep[r];
            float4 bk = s_box[k];
            e0 = s_val[k]; e1 = bk.x; e2 = bk.y; e3 = bk.z; e4 = bk.w;
        }
        float* row = outp + r * 5;
        row[0] = e0; row[1] = e1; row[2] = e2; row[3] = e3; row[4] = e4;
    }
    if (tid == 0) { g_cnt[bc] = 0; g_cntlow[bc] = 0; g_ovf[bc] = 0; }
}

// ---------------------------------------------------------------------------
extern "C" void kernel_launch(void* const* d_in, const int* in_sizes, int n_in,
                              void* d_out, int out_size) {
    const float *loc = nullptr, *conf = nullptr, *prior = nullptr;
    for (int i = 0; i < n_in; ++i) {
        long long sz = in_sizes[i];
        if      (sz == (long long)BATCH * PRIORS * 4)    loc   = (const float*)d_in[i];
        else if (sz == (long long)BATCH * PRIORS * NUMC) conf  = (const float*)d_in[i];
        else if (sz == (long long)PRIORS * 4)            prior = (const float*)d_in[i];
    }
    prep_gather<<<BATCH * PRIORS / NT, NT>>>(loc, conf, prior);
    nms_kernel<<<BATCH * NUMC, NT>>>((float*)d_out, conf);
    (void)out_size;
}

// round 17
// speedup vs baseline: 3.4150x; 1.3598x over previous
#include <cuda_runtime.h>
#include <cstdint>
#include <cstddef>

#define BATCH   32
#define PRIORS  32768
#define NUMC    21
#define NCLS    20
#define NMSK    1000
#define TOPK    200
#define CONF_T  0.01f
#define NMS_T   0.3f
#define NT      256
#define T0F     0.95f
#define CAP     2048
#define BCAP    64

typedef unsigned long long ull;
#define FULL 0xffffffffu

__device__ float4 g_decoded[(size_t)BATCH * PRIORS];
__device__ ull    g_cand[(size_t)BATCH * NCLS * CAP];
__device__ int    g_cnt[BATCH * NCLS];       // zero-init at load; self-zeroed by nms
__device__ int    g_cntlow[BATCH * NCLS];
__device__ int    g_ovf[BATCH * NCLS];

// ---------------------------------------------------------------------------
// Kernel 1: fused decode + candidate gather (one pass over conf, staged in smem)
// ---------------------------------------------------------------------------
__global__ __launch_bounds__(NT) void prep_gather(const float* __restrict__ loc,
                                                  const float* __restrict__ conf,
                                                  const float* __restrict__ prior) {
    __shared__ __align__(16) float s_stage[NT * NUMC];   // 21504 B
    __shared__ ull s_cbuf[NCLS][BCAP];                   // 10240 B
    __shared__ int s_ccnt[NCLS], s_lowc[NCLS];

    const int blk = blockIdx.x, tid = threadIdx.x, lane = tid & 31, wid = tid >> 5;

    const float4* src = reinterpret_cast<const float4*>(conf + (size_t)blk * NT * NUMC);
    float4* st = reinterpret_cast<float4*>(s_stage);
    for (int i = tid; i < NT * NUMC / 4; i += NT) st[i] = src[i];
    if (tid < NCLS) { s_ccnt[tid] = 0; s_lowc[tid] = 0; }

    const int idx = blk * NT + tid;
    const int p   = idx & (PRIORS - 1);
    const int b   = idx >> 15;
    {
        float4 l  = reinterpret_cast<const float4*>(loc)[idx];
        float4 pr = reinterpret_cast<const float4*>(prior)[p];
        float cx = pr.x + (l.x * 0.1f) * pr.z;
        float cy = pr.y + (l.y * 0.1f) * pr.w;
        float w  = pr.z * expf(l.z * 0.2f);
        float h  = pr.w * expf(l.w * 0.2f);
        float x1 = cx - w * 0.5f;
        float y1 = cy - h * 0.5f;
        g_decoded[idx] = make_float4(x1, y1, x1 + w, y1 + h);
    }
    __syncthreads();

    const float* row = s_stage + tid * NUMC;
#pragma unroll
    for (int c = 0; c < NCLS; ++c) {
        float x = row[c + 1];
        bool pass = (x > T0F);
        bool low  = (x > CONF_T) && !pass;
        unsigned int pm = __ballot_sync(FULL, pass);
        unsigned int lm = __ballot_sync(FULL, low);
        if (pm) {
            int leader = __ffs(pm) - 1;
            int n = __popc(pm);
            int base;
            if (lane == leader) base = atomicAdd(&s_ccnt[c], n);
            base = __shfl_sync(FULL, base, leader);
            if (pass) {
                int pos = base + __popc(pm & ((1u << lane) - 1u));
                if (pos < BCAP)
                    s_cbuf[c][pos] = ((ull)__float_as_uint(x) << 32)
                                   | (ull)(0xFFFFFFFFu - (unsigned int)p);
            }
        }
        if (lm && lane == __ffs(lm) - 1) atomicAdd(&s_lowc[c], __popc(lm));
    }
    __syncthreads();

    for (int c = wid; c < NCLS; c += 8) {
        int bc = b * NCLS + c;
        int n  = s_ccnt[c];
        int ov = (n > BCAP);
        if (ov) n = BCAP;
        int gbase;
        if (lane == 0) gbase = atomicAdd(&g_cnt[bc], n);
        gbase = __shfl_sync(FULL, gbase, 0);
        if (gbase + n > CAP) ov = 1;
        for (int i = lane; i < n; i += 32) {
            int q = gbase + i;
            if (q < CAP) g_cand[(size_t)bc * CAP + q] = s_cbuf[c][i];
        }
        if (lane == 0) {
            if (ov) atomicExch(&g_ovf[bc], 1);
            int lw = s_lowc[c];
            if (lw) atomicAdd(&g_cntlow[bc], lw);
        }
    }
}

// ---------------------------------------------------------------------------
// Kernel 2: per (batch,class) counting-sort top-1000 + batched greedy NMS
// ---------------------------------------------------------------------------
__global__ __launch_bounds__(NT) void nms_kernel(float* __restrict__ out,
                                                 const float* __restrict__ conf) {
    const int bx = blockIdx.x, b = bx / NUMC, cc = bx % NUMC;
    const int tid = threadIdx.x;
    float* outp = out + (size_t)bx * (TOPK * 5);

    if (cc == 0) {
        for (int i = tid; i < TOPK * 5; i += NT) outp[i] = 0.f;
        return;
    }
    const int bc = b * NCLS + (cc - 1);

    __shared__ __align__(16) unsigned char s_mem[28672];
    ull*    s_keys = reinterpret_cast<ull*>(s_mem);            // [0,16K)
    ull*    s_dst  = reinterpret_cast<ull*>(s_mem + 16384);    // [16K,24K)
    int*    s_hist = reinterpret_cast<int*>(s_mem);            // fallback alias
    float4* s_box  = reinterpret_cast<float4*>(s_mem);         // [0,16K) late
    float*  s_val  = reinterpret_cast<float*>(s_mem + 24576);  // [24K,28K)
    __shared__ int s_shist[256];
    __shared__ int s_off[257];
    __shared__ int s_cur[256];
    __shared__ float4 s_kbox[TOPK];
    __shared__ float  s_karea[TOPK];
    __shared__ int    s_keep[TOPK];
    __shared__ int    s_tri[32];
    __shared__ int    s_supin[32];
    __shared__ int s_cnt2, s_pivch, s_pivkk, s_pivbin, s_selb, s_sab, s_nk, s_bad;
    __shared__ unsigned int s_umax;

    const int lane = tid & 31;
    const int wid  = tid >> 5;

    int cnt = g_cnt[bc];
    bool need_fb = g_ovf[bc] || (cnt > CAP) || (cnt < NMSK && g_cntlow[bc] > 0);
    unsigned int Tgt = __float_as_uint(T0F);

    if (tid == 0) s_umax = 0u;
    __syncthreads();

    if (!need_fb) {
        const ull* cand = g_cand + (size_t)bc * CAP;
        unsigned int um = 0u;
        for (int i = tid; i < cnt; i += NT) {
            ull k = __ldg(cand + i);
            s_keys[i] = k;
            unsigned int bits = (unsigned int)(k >> 32);
            um = um > bits ? um : bits;
        }
#pragma unroll
        for (int o = 16; o; o >>= 1) {
            unsigned int t = __shfl_down_sync(FULL, um, o);
            um = um > t ? um : t;
        }
        if (lane == 0) atomicMax(&s_umax, um);
        __syncthreads();
    } else {
        // exact fallback: 12-bit histogram over strided raw conf column (rare)
        const float* base = conf + ((size_t)b << 15) * NUMC + cc;
        for (int i = tid; i < 4096; i += NT) s_hist[i] = 0;
        if (tid == 0) s_pivch = -1;
        __syncthreads();
        for (int i = tid; i < PRIORS; i += NT) {
            float x = __ldg(base + (size_t)i * NUMC);
            unsigned int bits = (x > CONF_T) ? __float_as_uint(x) : 0u;
            atomicAdd(&s_hist[bits >> 20], 1);
        }
        __syncthreads();
        { int cs = 0; for (int j = 0; j < 16; ++j) cs += s_hist[tid * 16 + j]; s_shist[tid] = cs; }
        __syncthreads();
        for (int d = 1; d < 256; d <<= 1) {
            int v = (tid + d < 256) ? s_shist[tid + d] : 0;
            __syncthreads();
            s_shist[tid] += v;
            __syncthreads();
        }
        { int suf = s_shist[tid]; int sufn = (tid < 255) ? s_shist[tid + 1] : 0;
          if (suf >= NMSK && sufn < NMSK) { s_pivch = tid; s_pivkk = NMSK - sufn; } }
        __syncthreads();
        if (tid == 0) {
            int pb = 1;
            if (s_pivch >= 0) {
                int ch = s_pivch, kk = s_pivkk, run = 0;
                for (int j = 15; j >= 0; --j) {
                    run += s_hist[ch * 16 + j];
                    if (run >= kk) { pb = ch * 16 + j; break; }
                }
            }
            if (pb < 1) pb = 1;
            s_pivbin = pb; s_cnt2 = 0; s_umax = 0u;
        }
        __syncthreads();
        Tgt = (((unsigned int)s_pivbin) << 20) - 1u;
        unsigned int um = 0u;
        for (int i = tid; i < PRIORS; i += NT) {
            float x = __ldg(base + (size_t)i * NUMC);
            unsigned int bits = __float_as_uint(x);
            if (x > CONF_T && bits > Tgt) {
                int pos = atomicAdd(&s_cnt2, 1);
                if (pos < CAP)
                    s_keys[pos] = ((ull)bits << 32) | (ull)(0xFFFFFFFFu - (unsigned int)i);
                um = um > bits ? um : bits;
            }
        }
#pragma unroll
        for (int o = 16; o; o >>= 1) {
            unsigned int t = __shfl_down_sync(FULL, um, o);
            um = um > t ? um : t;
        }
        if (lane == 0) atomicMax(&s_umax, um);
        __syncthreads();
        cnt = s_cnt2; if (cnt > CAP - 1) cnt = CAP - 1;
    }

    // ---------- counting sort of the top region (exact; fallback = bitonic) ----------
    int sabove;
    {
        const unsigned int base = Tgt;
        const unsigned int span = s_umax - base;
        const int nbits = 32 - __clz((int)(span | 1u));
        const int shift = nbits > 8 ? nbits - 8 : 0;
        s_shist[tid] = 0;
        if (tid == 0) { s_selb = 0; s_sab = cnt; s_bad = 0; s_off[256] = 0; }
        __syncthreads();
        for (int i = tid; i < cnt; i += NT) {
            unsigned int bits = (unsigned int)(s_keys[i] >> 32);
            atomicAdd(&s_shist[(bits - base) >> shift], 1);
        }
        __syncthreads();
        // suffix sums: s_off[b] = sum_{b'>=b} hist[b']
        s_off[tid] = s_shist[tid];
        __syncthreads();
        for (int d = 1; d < 256; d <<= 1) {
            int v = (tid + d < 256) ? s_off[tid + d] : 0;
            __syncthreads();
            s_off[tid] += v;
            __syncthreads();
        }
        { int suf = s_off[tid]; int sufn = (tid < 255) ? s_off[tid + 1] : 0;
          if (suf >= NMSK && sufn < NMSK) { s_selb = tid; s_sab = suf; } }
        __syncthreads();
        int selb = s_selb;
        if (tid >= selb && s_shist[tid] > 64) atomicExch(&s_bad, 1);
        __syncthreads();

        if (s_sab <= 1024 && !s_bad) {
            // cursors start at bin start offsets
            s_cur[tid] = s_off[tid + 1];
            for (int i = tid; i < 1024; i += NT) s_dst[i] = 0ull;
            __syncthreads();
            for (int i = tid; i < cnt; i += NT) {
                ull k = s_keys[i];
                unsigned int bits = (unsigned int)(k >> 32);
                int bin = (int)((bits - base) >> shift);
                if (bin >= selb) {
                    int pos = atomicAdd(&s_cur[bin], 1);
                    s_dst[pos] = k;
                }
            }
            __syncthreads();
            // per-bin insertion sort (descending by full 64-bit key)
            if (tid >= selb) {
                int st = s_off[tid + 1];
                int m  = s_shist[tid];
                for (int i2 = 1; i2 < m; ++i2) {
                    ull key = s_dst[st + i2];
                    int j = i2 - 1;
                    while (j >= 0 && s_dst[st + j] < key) {
                        s_dst[st + j + 1] = s_dst[st + j]; --j;
                    }
                    s_dst[st + j + 1] = key;
                }
            }
            __syncthreads();
            sabove = s_sab;
        } else {
            // rare fallback: full bitonic-2048 sort
            for (int i = cnt + tid; i < 2048; i += NT) s_keys[i] = 0ull;
            for (int k2 = 2; k2 <= 2048; k2 <<= 1) {
                for (int j = k2 >> 1; j > 0; j >>= 1) {
                    if (j >= 16) __syncthreads(); else __syncwarp();
                    for (int i = tid; i < 2048; i += NT) {
                        int l = i ^ j;
                        if (l > i) {
                            ull a = s_keys[i], bb = s_keys[l];
                            bool up = ((i & k2) == 0);
                            if (up ? (a < bb) : (a > bb)) { s_keys[i] = bb; s_keys[l] = a; }
                        }
                    }
                }
            }
            __syncthreads();
            for (int i = tid; i < 1024; i += NT) s_dst[i] = (i < NMSK) ? s_keys[i] : 0ull;
            __syncthreads();
            sabove = cnt;
        }
    }

    // ---------- extract boxes (s_box aliases dead s_keys) ----------
    const float4* dec = g_decoded + ((size_t)b << 15);
    const int nvalid = sabove < NMSK ? sabove : NMSK;
    for (int r = tid; r < 1024; r += NT) {
        float v = 0.f;
        float4 bb = make_float4(0.f, 0.f, 0.f, 0.f);
        if (r < NMSK) {
            ull key = s_dst[r];
            unsigned int bits = (unsigned int)(key >> 32);
            v = __uint_as_float(bits);
            if (v > CONF_T) {
                unsigned int p = 0xFFFFFFFFu - (unsigned int)(key & 0xFFFFFFFFull);
                bb = __ldg(dec + p);
            } else v = 0.f;
        }
        s_box[r] = bb;
        s_val[r] = v;
    }
    __syncthreads();

    // ---------- batched-speculative greedy NMS (exact; 32 candidates/batch) ----------
    int nk = 0;
    const int nbatch = (nvalid + 31) >> 5;
    for (int bt = 0; bt < nbatch; ++bt) {
        const int B0 = bt << 5;
        if (s_val[B0] <= CONF_T) break;          // sorted: rest invalid (uniform)
        if (tid < 32) { s_supin[tid] = 0; s_tri[tid] = 0; }
        __syncthreads();

        // Phase 1: kept-set tests + intra-batch triangle strips
        {
            int c = B0 + lane;
            float vc = s_val[c];
            if (vc > CONF_T) {
                float4 bcx = s_box[c];
                float acx = (bcx.z - bcx.x) * (bcx.w - bcx.y);
                bool sup = false;
                for (int j = wid; j < nk; j += 8) {
                    float4 ba = s_kbox[j];          // broadcast across lanes
                    float w = fminf(bcx.z, ba.z) - fmaxf(bcx.x, ba.x);
                    float h = fminf(bcx.w, ba.w) - fmaxf(bcx.y, ba.y);
                    w = fmaxf(w, 0.f); h = fmaxf(h, 0.f);
                    float inter = w * h;
                    sup = sup || (inter / (acx + s_karea[j] - inter) > NMS_T);
                }
                if (sup) s_supin[lane] = 1;         // benign race (same value)
                // intra-batch triangle: predecessors a == wid (mod 8), a < lane
                for (int a = wid; a < lane; a += 8) {
                    float4 ba = s_box[B0 + a];
                    float w = fminf(bcx.z, ba.z) - fmaxf(bcx.x, ba.x);
                    float h = fminf(bcx.w, ba.w) - fmaxf(bcx.y, ba.y);
                    w = fmaxf(w, 0.f); h = fmaxf(h, 0.f);
                    float inter = w * h;
                    float aa = (ba.z - ba.x) * (ba.w - ba.y);
                    if (inter / (acx + aa - inter) > NMS_T)
                        atomicOr(&s_tri[lane], 1 << a);
                }
            }
        }
        __syncthreads();

        // Phase 2: warp 0 — greedy chain replay + append keeps
        if (wid == 0) {
            int c = B0 + lane;
            float4 bcx = s_box[c];
            float vc = s_val[c];
            float acx = (bcx.z - bcx.x) * (bcx.w - bcx.y);
            unsigned int vmask = __ballot_sync(FULL, vc > CONF_T);
            unsigned int supin = __ballot_sync(FULL, s_supin[lane] != 0);
            unsigned int kept = 0;
            unsigned int elig = vmask & ~supin;
            int cap = TOPK - nk;
            int c2 = 0;
#pragma unroll 4
            for (int a = 0; a < 32; ++a) {
                if (c2 < cap && ((elig >> a) & 1u)
                    && (((unsigned int)s_tri[a] & kept) == 0u)) {
                    kept |= 1u << a; ++c2;
                }
            }
            if ((kept >> lane) & 1u) {
                int r = nk + __popc(kept & ((1u << lane) - 1u));
                s_kbox[r] = bcx; s_karea[r] = acx; s_keep[r] = c;
            }
            if (lane == 0) s_nk = nk + c2;
        }
        __syncthreads();
        nk = s_nk;
        if (nk >= TOPK) break;
    }
    __syncthreads();

    // ---------- write output + self-zero counters ----------
    int nkeep = nk < TOPK ? nk : TOPK;
    for (int r = tid; r < TOPK; r += NT) {
        float e0 = 0.f, e1 = 0.f, e2 = 0.f, e3 = 0.f, e4 = 0.f;
        if (r < nkeep) {
            int k = s_keep[r];
            float4 bk = s_box[k];
            e0 = s_val[k]; e1 = bk.x; e2 = bk.y; e3 = bk.z; e4 = bk.w;
        }
        float* row = outp + r * 5;
        row[0] = e0; row[1] = e1; row[2] = e2; row[3] = e3; row[4] = e4;
    }
    if (tid == 0) { g_cnt[bc] = 0; g_cntlow[bc] = 0; g_ovf[bc] = 0; }
}

// ---------------------------------------------------------------------------
extern "C" void kernel_launch(void* const* d_in, const int* in_sizes, int n_in,
                              void* d_out, int out_size) {
    const float *loc = nullptr, *conf = nullptr, *prior = nullptr;
    for (int i = 0; i < n_in; ++i) {
        long long sz = in_sizes[i];
        if      (sz == (long long)BATCH * PRIORS * 4)    loc   = (const float*)d_in[i];
        else if (sz == (long long)BATCH * PRIORS * NUMC) conf  = (const float*)d_in[i];
        else if (sz == (long long)PRIORS * 4)            prior = (const float*)d_in[i];
    }
    prep_gather<<<BATCH * PRIORS / NT, NT>>>(loc, conf, prior);
    nms_kernel<<<BATCH * NUMC, NT>>>((float*)d_out, conf);
    (void)out_size;
}